// round 1
// baseline (speedup 1.0000x reference)
#include <cuda_runtime.h>

#define S_LEN   2048
#define LOG_S   11
#define NCH     64
#define NB      16
#define CHUNK   128
#define NSC     (S_LEN / CHUNK)        // 16 sample-chunks
#define PLI_THREADS 512
#define NWARPS  (PLI_THREADS / 32)
#define FFT_THREADS 256

// Scratch (static __device__ allocation — allowed by harness rules)
__device__ float2 g_analytic[NB * NCH * S_LEN];   // 16 MB
__device__ int    g_cnt[NB * NCH * NCH];          // 256 KB of int counters

// ---------------------------------------------------------------------------
// Kernel 0: zero the counters (out/d scratch is poisoned each run)
// ---------------------------------------------------------------------------
__global__ void zero_cnt_kernel() {
    int idx = blockIdx.x * blockDim.x + threadIdx.x;
    if (idx < NB * NCH * NCH) g_cnt[idx] = 0;
}

// ---------------------------------------------------------------------------
// Kernel 1: Hilbert analytic signal per channel via shared-memory FFT.
// One block per (b,c) channel. Radix-2 iterative DIT, bit-reversed input,
// natural-order output. Twiddle table in smem (precise sincosf, computed once).
// Skips the 1/N IFFT scaling: PLI only uses signs of cross products.
// ---------------------------------------------------------------------------
__device__ __forceinline__ void fft_stages(float2* buf, const float2* tw,
                                           int tid, bool inv) {
    #pragma unroll
    for (int p = 1; p <= LOG_S; p++) {
        const int half  = 1 << (p - 1);
        const int twsh  = LOG_S - p;       // twiddle index = j << twsh
        #pragma unroll 4
        for (int t = tid; t < (S_LEN / 2); t += FFT_THREADS) {
            int blk = t >> (p - 1);
            int j   = t & (half - 1);
            int i0  = (blk << p) + j;
            int i1  = i0 + half;
            float2 w = tw[j << twsh];
            float wy = inv ? -w.y : w.y;
            float2 u = buf[i0];
            float2 v = buf[i1];
            float vwx = v.x * w.x - v.y * wy;
            float vwy = v.x * wy + v.y * w.x;
            buf[i0] = make_float2(u.x + vwx, u.y + vwy);
            buf[i1] = make_float2(u.x - vwx, u.y - vwy);
        }
        __syncthreads();
    }
}

__global__ __launch_bounds__(FFT_THREADS)
void hilbert_kernel(const float* __restrict__ x) {
    __shared__ float2 buf [S_LEN];
    __shared__ float2 buf2[S_LEN];
    __shared__ float2 tw  [S_LEN / 2];

    const int bc  = blockIdx.x;               // b*64 + c, 0..1023
    const int tid = threadIdx.x;
    const float* xin = x + (size_t)bc * S_LEN;

    // twiddles: tw[k] = exp(-2*pi*i*k / S)
    for (int k = tid; k < S_LEN / 2; k += FFT_THREADS) {
        float ang = (-6.283185307179586f / (float)S_LEN) * (float)k;
        float sn, cs;
        sincosf(ang, &sn, &cs);
        tw[k] = make_float2(cs, sn);
    }
    // load input bit-reversed, imaginary part 0
    for (int i = tid; i < S_LEN; i += FFT_THREADS) {
        int rev = __brev((unsigned)i) >> (32 - LOG_S);
        buf[rev] = make_float2(xin[i], 0.0f);
    }
    __syncthreads();

    fft_stages(buf, tw, tid, false);          // forward FFT, natural order out

    // Hilbert filter: h[0]=1, h[S/2]=1, h[1..S/2-1]=2, rest 0.
    // Write filtered spectrum bit-reversed into buf2 for the inverse pass.
    for (int k = tid; k < S_LEN; k += FFT_THREADS) {
        float2 v = buf[k];
        float h = (k == 0 || k == S_LEN / 2) ? 1.0f
                 : (k < S_LEN / 2 ? 2.0f : 0.0f);
        int rev = __brev((unsigned)k) >> (32 - LOG_S);
        buf2[rev] = make_float2(v.x * h, v.y * h);
    }
    __syncthreads();

    fft_stages(buf2, tw, tid, true);          // inverse FFT (unnormalized)

    float2* dst = g_analytic + (size_t)bc * S_LEN;
    for (int i = tid; i < S_LEN; i += FFT_THREADS)
        dst[i] = buf2[i];
}

// ---------------------------------------------------------------------------
// Kernel 2: pairwise sign counting.
// Block = (sample-chunk sc, batch b). Stages all 64 channels x CHUNK samples
// in smem. Each warp owns 4x4 channel-pair tiles (upper triangle of 16x16
// tile grid = 136 tiles, strided across 16 warps). Lanes = samples.
// sign(sin(ti - tj)) == sign(y_i*x_j - x_i*y_j); counted via ballot+popc.
// ---------------------------------------------------------------------------
__global__ __launch_bounds__(PLI_THREADS)
void pli_kernel() {
    extern __shared__ float2 sdata[];                 // [NCH][CHUNK]
    const int sc  = blockIdx.x;                       // 0..NSC-1
    const int b   = blockIdx.y;                       // 0..NB-1
    const int tid = threadIdx.x;

    // Stage channels into smem with float4 (2 samples per load)
    const float4* gsrc = reinterpret_cast<const float4*>(g_analytic);
    float4* ssh = reinterpret_cast<float4*>(sdata);
    for (int k = tid; k < NCH * (CHUNK / 2); k += PLI_THREADS) {
        int c  = k / (CHUNK / 2);
        int sp = k - c * (CHUNK / 2);
        size_t gi = (((size_t)(b * NCH + c)) * S_LEN + (size_t)sc * CHUNK) / 2 + sp;
        ssh[c * (CHUNK / 2) + sp] = gsrc[gi];
    }
    __syncthreads();

    const int warp = tid >> 5;
    const int lane = tid & 31;

    for (int t = warp; t < 136; t += NWARPS) {
        // decode triangular tile index -> (ti, tj), ti <= tj
        int ti = 0, rem = t;
        while (rem >= (16 - ti)) { rem -= (16 - ti); ti++; }
        int tj = ti + rem;

        const float2* rowi = sdata + (ti * 4) * CHUNK;
        const float2* rowj = sdata + (tj * 4) * CHUNK;

        int acc[16];
        #pragma unroll
        for (int q = 0; q < 16; q++) acc[q] = 0;

        #pragma unroll
        for (int it = 0; it < CHUNK / 32; it++) {
            int s = it * 32 + lane;
            float2 ai[4], aj[4];
            #pragma unroll
            for (int a = 0; a < 4; a++) ai[a] = rowi[a * CHUNK + s];
            #pragma unroll
            for (int a = 0; a < 4; a++) aj[a] = rowj[a * CHUNK + s];

            #pragma unroll
            for (int a = 0; a < 4; a++) {
                #pragma unroll
                for (int c2 = 0; c2 < 4; c2++) {
                    // cross = y_i*x_j - x_i*y_j   (FMUL + FFMA, neg folded)
                    float p     = ai[a].x * aj[c2].y;
                    float cross = fmaf(ai[a].y, aj[c2].x, -p);
                    unsigned mp = __ballot_sync(0xffffffffu, cross > 0.0f);
                    unsigned mn = __ballot_sync(0xffffffffu, cross < 0.0f);
                    acc[a * 4 + c2] += __popc(mp) - __popc(mn);
                }
            }
        }

        if (lane == 0) {
            #pragma unroll
            for (int a = 0; a < 4; a++) {
                #pragma unroll
                for (int c2 = 0; c2 < 4; c2++) {
                    atomicAdd(&g_cnt[(b * NCH + ti * 4 + a) * NCH + tj * 4 + c2],
                              acc[a * 4 + c2]);
                }
            }
        }
    }
}

// ---------------------------------------------------------------------------
// Kernel 3: finalize |count|/S into output; zero diagonal; mirror i>j.
// (diagonal counters are FMA-rounding noise — never read them)
// ---------------------------------------------------------------------------
__global__ void finalize_kernel(float* __restrict__ out) {
    int idx = blockIdx.x * blockDim.x + threadIdx.x;
    if (idx >= NB * NCH * NCH) return;
    int b = idx >> 12;
    int i = (idx >> 6) & 63;
    int j = idx & 63;
    float v = 0.0f;
    if (i != j) {
        int c = (i < j) ? g_cnt[(b * NCH + i) * NCH + j]
                        : g_cnt[(b * NCH + j) * NCH + i];
        v = fabsf((float)c) * (1.0f / (float)S_LEN);
    }
    out[idx] = v;
}

// ---------------------------------------------------------------------------
extern "C" void kernel_launch(void* const* d_in, const int* in_sizes, int n_in,
                              void* d_out, int out_size) {
    const float* x = (const float*)d_in[0];
    float* out = (float*)d_out;

    (void)in_sizes; (void)n_in; (void)out_size;

    const int smem_bytes = NCH * CHUNK * (int)sizeof(float2);   // 64 KB
    cudaFuncSetAttribute(pli_kernel,
                         cudaFuncAttributeMaxDynamicSharedMemorySize,
                         smem_bytes);

    zero_cnt_kernel<<<(NB * NCH * NCH + 1023) / 1024, 1024>>>();
    hilbert_kernel<<<NB * NCH, FFT_THREADS>>>(x);
    pli_kernel<<<dim3(NSC, NB), PLI_THREADS, smem_bytes>>>();
    finalize_kernel<<<(NB * NCH * NCH + 255) / 256, 256>>>(out);
}

// round 2
// speedup vs baseline: 2.0198x; 2.0198x over previous
#include <cuda_runtime.h>

#define S_LEN   2048
#define NCH     64
#define NB      16
#define CHUNK   128
#define NSC     (S_LEN / CHUNK)        // 16 sample-chunks
#define PLI_THREADS 512
#define NWARPS  (PLI_THREADS / 32)
#define FFT_THREADS 256

// Scratch (static __device__ allocation — allowed by harness rules)
__device__ float2 g_analytic[NB * NCH * S_LEN];   // 16 MB
__device__ int    g_cnt[NB * NCH * NCH];          // 256 KB of int counters

// ---------------------------------------------------------------------------
// Kernel 0: zero the counters. Kept as a standalone (cheap) launch so that the
// ncu skip-count (-s 5) lands on hilbert_kernel next capture.
// ---------------------------------------------------------------------------
__global__ void zero_cnt_kernel() {
    int idx = blockIdx.x * blockDim.x + threadIdx.x;
    if (idx < NB * NCH * NCH) g_cnt[idx] = 0;
}

// ---------------------------------------------------------------------------
// Radix-4 Stockham autosort FFT pieces (N = 2048 = 2 * 4^5).
// DIF formulation; natural-order in, natural-order out; ping-pong buffers.
// ---------------------------------------------------------------------------
__device__ __forceinline__ float2 cmul(float2 a, float2 b) {
    return make_float2(fmaf(a.x, b.x, -a.y * b.y),
                       fmaf(a.x, b.y,  a.y * b.x));
}

// radix-2 stage: l = 1024, m = 1  (first stage)
template<bool INV>
__device__ __forceinline__ void stage_r2(const float2* __restrict__ src,
                                         float2* __restrict__ dst,
                                         const float2* __restrict__ tw,
                                         int tid) {
    #pragma unroll
    for (int p = tid; p < 1024; p += FFT_THREADS) {
        float2 w = tw[p];                       // exp(-2*pi*i p/2048)
        if (INV) w.y = -w.y;
        float2 a = src[p];
        float2 b = src[p + 1024];
        float2 s = make_float2(a.x + b.x, a.y + b.y);
        float2 d = make_float2(a.x - b.x, a.y - b.y);
        dst[2 * p]     = s;
        dst[2 * p + 1] = cmul(w, d);
    }
}

// radix-4 stage: L * M * 4 == 2048
template<int L, int LOG2M, bool INV>
__device__ __forceinline__ void stage_r4(const float2* __restrict__ src,
                                         float2* __restrict__ dst,
                                         const float2* __restrict__ tw,
                                         int tid) {
    constexpr int M   = 1 << LOG2M;
    constexpr int TWS = 512 / L;                // twiddle stride
    #pragma unroll
    for (int t = tid; t < 512; t += FFT_THREADS) {
        const int p = t >> LOG2M;
        const int q = t & (M - 1);
        const int ib = q + M * p;               // == t
        float2 a = src[ib];
        float2 b = src[ib + M * L];
        float2 c = src[ib + 2 * M * L];
        float2 d = src[ib + 3 * M * L];

        float2 w1 = tw[p * TWS];                // exp(-2*pi*i p/(4L))
        float2 w2 = tw[2 * p * TWS];
        if (INV) { w1.y = -w1.y; w2.y = -w2.y; }
        float2 w3 = cmul(w1, w2);

        float2 t0 = make_float2(a.x + c.x, a.y + c.y);
        float2 t1 = make_float2(a.x - c.x, a.y - c.y);
        float2 t2 = make_float2(b.x + d.x, b.y + d.y);
        float2 e  = make_float2(b.x - d.x, b.y - d.y);
        // forward: t3 = -i*e ; inverse: t3 = +i*e
        float2 t3 = INV ? make_float2(-e.y,  e.x)
                        : make_float2( e.y, -e.x);

        const int ob = q + 4 * M * p;
        dst[ob]         = make_float2(t0.x + t2.x, t0.y + t2.y);
        dst[ob + M]     = cmul(w1, make_float2(t1.x + t3.x, t1.y + t3.y));
        dst[ob + 2 * M] = cmul(w2, make_float2(t0.x - t2.x, t0.y - t2.y));
        dst[ob + 3 * M] = cmul(w3, make_float2(t1.x - t3.x, t1.y - t3.y));
    }
}

template<bool INV>
__device__ __forceinline__ void fft2048(float2* __restrict__ A,
                                        float2* __restrict__ B,
                                        const float2* __restrict__ tw,
                                        int tid) {
    // A -> B -> A -> B -> A -> B -> A  (result lands back in A)
    stage_r2<INV>(A, B, tw, tid);                 __syncthreads();
    stage_r4<256, 1, INV>(B, A, tw, tid);         __syncthreads();
    stage_r4< 64, 3, INV>(A, B, tw, tid);         __syncthreads();
    stage_r4< 16, 5, INV>(B, A, tw, tid);         __syncthreads();
    stage_r4<  4, 7, INV>(A, B, tw, tid);         __syncthreads();
    stage_r4<  1, 9, INV>(B, A, tw, tid);         __syncthreads();
}

// ---------------------------------------------------------------------------
// Kernel 1: Hilbert analytic signal, 2 channels per block.
// z = x0 + i*x1 -> one forward FFT; unpack spectra with conjugate symmetry;
// apply h (k=0,N/2 -> 1 ; 1..N/2-1 -> 2 ; else 0); two inverse FFTs.
// All positive real global scale factors (1/2, 1/N) dropped: PLI uses only
// signs of cross products. The -i rotation on channel 1 IS applied exactly.
// ---------------------------------------------------------------------------
__global__ __launch_bounds__(FFT_THREADS)
void hilbert_kernel(const float* __restrict__ x) {
    extern __shared__ float2 smem[];
    float2* A  = smem;                 // 2048
    float2* B  = smem + 2048;          // 2048
    float2* C  = smem + 4096;          // 2048
    float2* tw = smem + 6144;          // 1024

    const int tid = threadIdx.x;
    const int blk = blockIdx.x;                 // 0..511
    const int b   = blk >> 5;                   // batch
    const int cp  = blk & 31;                   // channel pair
    const int ch0 = b * NCH + 2 * cp;

    const float* __restrict__ x0 = x + (size_t)ch0 * S_LEN;
    const float* __restrict__ x1 = x0 + S_LEN;

    // twiddles tw[k] = exp(-2*pi*i k / 2048), k = 0..1023
    for (int k = tid; k < 1024; k += FFT_THREADS) {
        float sn, cs;
        sincosf((-6.283185307179586f / 2048.0f) * (float)k, &sn, &cs);
        tw[k] = make_float2(cs, sn);
    }
    // pack two real channels into one complex signal
    for (int i = tid; i < S_LEN; i += FFT_THREADS)
        A[i] = make_float2(x0[i], x1[i]);
    __syncthreads();

    fft2048<false>(A, B, tw, tid);              // Z in A (natural order)

    // unpack + Hilbert filter:
    //   G0[k] = h[k] * (Z[k] + conj(Z[N-k]))          (drop 1/2)
    //   G1[k] = h[k] * (-i) * (Z[k] - conj(Z[N-k]))   (drop 1/2)
    for (int k = tid; k < S_LEN; k += FFT_THREADS) {
        if (k <= 1024) {
            float2 zk = A[k];
            float2 zm = A[(S_LEN - k) & (S_LEN - 1)];
            float  h  = (k == 0 || k == 1024) ? 1.0f : 2.0f;
            B[k] = make_float2(h * (zk.x + zm.x), h * (zk.y - zm.y));
            // e = zk - conj(zm) = (zk.x - zm.x, zk.y + zm.y); -i*e = (e.y, -e.x)
            C[k] = make_float2(h * (zk.y + zm.y), -h * (zk.x - zm.x));
        } else {
            B[k] = make_float2(0.0f, 0.0f);
            C[k] = make_float2(0.0f, 0.0f);
        }
    }
    __syncthreads();

    // inverse FFTs (unnormalized); A is free scratch now
    fft2048<true>(B, A, tw, tid);               // analytic ch0 in B
    float2* __restrict__ d0 = g_analytic + (size_t)ch0 * S_LEN;
    for (int i = tid; i < S_LEN; i += FFT_THREADS) d0[i] = B[i];
    __syncthreads();

    fft2048<true>(C, A, tw, tid);               // analytic ch1 in C
    float2* __restrict__ d1 = d0 + S_LEN;
    for (int i = tid; i < S_LEN; i += FFT_THREADS) d1[i] = C[i];
}

// ---------------------------------------------------------------------------
// Kernel 2: pairwise sign counting.
// sign(sin(ti - tj)) == sign(y_i*x_j - x_i*y_j). Lanes = samples; ONE ballot
// per pair-sample-group counts positives P; sumsign = 2P - n (exact zeros,
// probability ~2^-24, land as -1 — negligible vs 1e-3 tolerance).
// ---------------------------------------------------------------------------
__global__ __launch_bounds__(PLI_THREADS)
void pli_kernel() {
    extern __shared__ float2 sdata[];                 // [NCH][CHUNK]
    const int sc  = blockIdx.x;
    const int b   = blockIdx.y;
    const int tid = threadIdx.x;

    const float4* gsrc = reinterpret_cast<const float4*>(g_analytic);
    float4* ssh = reinterpret_cast<float4*>(sdata);
    for (int k = tid; k < NCH * (CHUNK / 2); k += PLI_THREADS) {
        int c  = k / (CHUNK / 2);
        int sp = k - c * (CHUNK / 2);
        size_t gi = (((size_t)(b * NCH + c)) * S_LEN + (size_t)sc * CHUNK) / 2 + sp;
        ssh[c * (CHUNK / 2) + sp] = gsrc[gi];
    }
    __syncthreads();

    const int warp = tid >> 5;
    const int lane = tid & 31;

    for (int t = warp; t < 136; t += NWARPS) {
        int ti = 0, rem = t;
        while (rem >= (16 - ti)) { rem -= (16 - ti); ti++; }
        int tj = ti + rem;

        const float2* rowi = sdata + (ti * 4) * CHUNK;
        const float2* rowj = sdata + (tj * 4) * CHUNK;

        int acc[16];
        #pragma unroll
        for (int q = 0; q < 16; q++) acc[q] = 0;

        #pragma unroll
        for (int it = 0; it < CHUNK / 32; it++) {
            int s = it * 32 + lane;
            float2 ai[4], aj[4];
            #pragma unroll
            for (int a = 0; a < 4; a++) ai[a] = rowi[a * CHUNK + s];
            #pragma unroll
            for (int a = 0; a < 4; a++) aj[a] = rowj[a * CHUNK + s];

            #pragma unroll
            for (int a = 0; a < 4; a++) {
                #pragma unroll
                for (int c2 = 0; c2 < 4; c2++) {
                    float p     = ai[a].x * aj[c2].y;
                    float cross = fmaf(ai[a].y, aj[c2].x, -p);
                    unsigned mp = __ballot_sync(0xffffffffu, cross > 0.0f);
                    acc[a * 4 + c2] += __popc(mp);
                }
            }
        }

        if (lane == 0) {
            #pragma unroll
            for (int a = 0; a < 4; a++)
                #pragma unroll
                for (int c2 = 0; c2 < 4; c2++)
                    atomicAdd(&g_cnt[(b * NCH + ti * 4 + a) * NCH + tj * 4 + c2],
                              acc[a * 4 + c2]);
        }
    }
}

// ---------------------------------------------------------------------------
// Kernel 3: finalize |2P - S| / S ; zero diagonal; mirror i>j.
// ---------------------------------------------------------------------------
__global__ void finalize_kernel(float* __restrict__ out) {
    int idx = blockIdx.x * blockDim.x + threadIdx.x;
    if (idx >= NB * NCH * NCH) return;
    int b = idx >> 12;
    int i = (idx >> 6) & 63;
    int j = idx & 63;
    float v = 0.0f;
    if (i != j) {
        int c = (i < j) ? __ldg(&g_cnt[(b * NCH + i) * NCH + j])
                        : __ldg(&g_cnt[(b * NCH + j) * NCH + i]);
        v = fabsf(2.0f * (float)c - (float)S_LEN) * (1.0f / (float)S_LEN);
    }
    out[idx] = v;
}

// ---------------------------------------------------------------------------
extern "C" void kernel_launch(void* const* d_in, const int* in_sizes, int n_in,
                              void* d_out, int out_size) {
    const float* x = (const float*)d_in[0];
    float* out = (float*)d_out;
    (void)in_sizes; (void)n_in; (void)out_size;

    const int fft_smem = (3 * 2048 + 1024) * (int)sizeof(float2);   // 57344 B
    const int pli_smem = NCH * CHUNK * (int)sizeof(float2);         // 65536 B
    cudaFuncSetAttribute(hilbert_kernel,
                         cudaFuncAttributeMaxDynamicSharedMemorySize, fft_smem);
    cudaFuncSetAttribute(pli_kernel,
                         cudaFuncAttributeMaxDynamicSharedMemorySize, pli_smem);

    zero_cnt_kernel<<<(NB * NCH * NCH + 1023) / 1024, 1024>>>();
    hilbert_kernel<<<NB * NCH / 2, FFT_THREADS, fft_smem>>>(x);
    pli_kernel<<<dim3(NSC, NB), PLI_THREADS, pli_smem>>>();
    finalize_kernel<<<(NB * NCH * NCH + 255) / 256, 256>>>(out);
}